// round 2
// baseline (speedup 1.0000x reference)
#include <cuda_runtime.h>
#include <cstdint>

// ============================================================================
// Two tf32 mma.sync GEMMs (tcgen05 unavailable: harness targets plain sm_100):
//   K1: meas = cumprod8(cos(x @ Wq^T))   -> g_meas scratch
//   K2: out  = meas @ Wo^T               -> d_out
// k = x@Wk^T and v = x@Wv^T are dead compute in the reference; skipped.
// Both einsums are D[m,n] = sum_k A[m,k]*W[n,k]  (K-major x K-major)
//   -> mma.sync.aligned.m16n8k8.row.col.f32.tf32.tf32.f32
// ============================================================================

#define BM 128
#define BN 128
#define BK 32
#define KTOT 512
#define MTOT 32768
#define NCHUNK (KTOT / BK)          // 16

#define ASTRIDE 36                  // floats per smem row: 32 + 4 pad (bank-safe)
#define TILE_FLOATS (BM * ASTRIDE)  // 4608
#define STAGE_FLOATS (2 * TILE_FLOATS)
#define SMEM_BYTES (2 * STAGE_FLOATS * 4)  // 2 stages: 73728 B

// 64 MB intermediate scratch (device global array: no runtime allocation)
__device__ float g_meas[(size_t)MTOT * KTOT];

// ---------------------------------------------------------------------------
static __device__ __forceinline__ uint32_t smem_u32(const void* p) {
    uint32_t a;
    asm("{ .reg .u64 t; cvta.to.shared.u64 t, %1; cvt.u32.u64 %0, t; }"
        : "=r"(a) : "l"(p));
    return a;
}

// fp32 -> tf32 with round-to-nearest (unbiased; truncation would bias -5e-4)
static __device__ __forceinline__ uint32_t f2tf(float f) {
    uint32_t u;
    asm("cvt.rna.tf32.f32 %0, %1;" : "=r"(u) : "f"(f));
    return u;
}

static __device__ __forceinline__ void cp_async16(uint32_t dst, const void* src) {
    asm volatile("cp.async.cg.shared.global [%0], [%1], 16;"
                 :: "r"(dst), "l"(src) : "memory");
}
static __device__ __forceinline__ void cp_commit() {
    asm volatile("cp.async.commit_group;" ::: "memory");
}
static __device__ __forceinline__ void cp_wait1() {
    asm volatile("cp.async.wait_group 1;" ::: "memory");
}

static __device__ __forceinline__ void mma_tf32(float* c, const uint32_t* a,
                                                const uint32_t* b) {
    asm volatile(
        "mma.sync.aligned.m16n8k8.row.col.f32.tf32.tf32.f32 "
        "{%0,%1,%2,%3}, {%4,%5,%6,%7}, {%8,%9}, {%0,%1,%2,%3};"
        : "+f"(c[0]), "+f"(c[1]), "+f"(c[2]), "+f"(c[3])
        : "r"(a[0]), "r"(a[1]), "r"(a[2]), "r"(a[3]), "r"(b[0]), "r"(b[1]));
}

// Exclusive-prefix cumprod of cos over one 8-wide head held by a lane quad.
// Thread (tig = lane&3) holds cols 2*tig, 2*tig+1 of its row.
static __device__ __forceinline__ float2 head_scan(float v0, float v1, int tig) {
    const float c0 = __cosf(v0);
    const float c1 = __cosf(v1);
    const float p = c0 * c1;
    const float pm1 = __shfl_up_sync(0xffffffffu, p, 1, 4);
    const float pm2 = __shfl_up_sync(0xffffffffu, p, 2, 4);
    const float pm3 = __shfl_up_sync(0xffffffffu, p, 3, 4);
    float ex = 1.0f;
    if (tig >= 1) ex *= pm1;
    if (tig >= 2) ex *= pm2;
    if (tig >= 3) ex *= pm3;
    float2 r;
    r.x = ex * c0;      // cumprod through col 2*tig
    r.y = ex * p;       // cumprod through col 2*tig+1
    return r;
}

// ---------------------------------------------------------------------------
// D[m_base.., n_base..] = A . W^T over K=512.  4 warps, warp tile 64x64.
// MEASURE: epilogue = cos+cumprod8 along n -> g_meas.  else -> Outp raw.
// ---------------------------------------------------------------------------
template <bool MEASURE>
__global__ void __launch_bounds__(128, 2) qgemm(
    const float* __restrict__ Ain,
    const float* __restrict__ W,
    float* __restrict__ Outp) {
    extern __shared__ float sm[];
    const uint32_t sb = smem_u32(sm);
    const int tid = threadIdx.x;
    const int wid = tid >> 5;
    const int lane = tid & 31;
    const int g = lane >> 2;       // group id (row within fragment)
    const int tig = lane & 3;      // thread-in-group (k / col-pair selector)

    // N-tiles vary fastest (blockIdx.x) so wave-adjacent CTAs share A rows in L2
    const int n_base = blockIdx.x * BN;
    const int m_base = blockIdx.y * BM;

    const float* __restrict__ A = MEASURE ? Ain : g_meas;

    const int ldrow = tid >> 3;        // 0..15? no: 128 thr, p>>3 below
    (void)ldrow;

    // ---- async stage loader: A tile 128x32 + B tile 128x32, 16B chunks ----
    auto load_stage = [&](int s, int kb) {
        const uint32_t sa = sb + (uint32_t)(s * STAGE_FLOATS) * 4u;
        const uint32_t sw = sa + (uint32_t)TILE_FLOATS * 4u;
#pragma unroll
        for (int i = 0; i < 8; i++) {
            const int p = tid + i * 128;
            const int row = p >> 3;
            const int c = p & 7;
            cp_async16(sa + (uint32_t)(row * ASTRIDE + c * 4) * 4u,
                       A + (size_t)(m_base + row) * KTOT + kb + c * 4);
        }
#pragma unroll
        for (int i = 0; i < 8; i++) {
            const int p = tid + i * 128;
            const int row = p >> 3;
            const int c = p & 7;
            cp_async16(sw + (uint32_t)(row * ASTRIDE + c * 4) * 4u,
                       W + (size_t)(n_base + row) * KTOT + kb + c * 4);
        }
        cp_commit();
    };

    load_stage(0, 0);
    load_stage(1, BK);

    const int warp_m = wid & 1;    // 2 x 64 rows
    const int warp_n = wid >> 1;   // 2 x 64 cols

    float acc[4][8][4];
#pragma unroll
    for (int mt = 0; mt < 4; mt++)
#pragma unroll
        for (int nt = 0; nt < 8; nt++)
#pragma unroll
            for (int i = 0; i < 4; i++) acc[mt][nt][i] = 0.0f;

#pragma unroll 1
    for (int kc = 0; kc < NCHUNK; kc++) {
        cp_wait1();
        __syncthreads();
        const float* smA = sm + (kc & 1) * STAGE_FLOATS;
        const float* smB = smA + TILE_FLOATS;

#pragma unroll
        for (int ks = 0; ks < 4; ks++) {
            const int k0 = ks * 8 + tig;
            uint32_t af[4][4];
            uint32_t bf[8][2];
#pragma unroll
            for (int mt = 0; mt < 4; mt++) {
                const int r = warp_m * 64 + mt * 16 + g;
                af[mt][0] = f2tf(smA[r * ASTRIDE + k0]);
                af[mt][1] = f2tf(smA[(r + 8) * ASTRIDE + k0]);
                af[mt][2] = f2tf(smA[r * ASTRIDE + k0 + 4]);
                af[mt][3] = f2tf(smA[(r + 8) * ASTRIDE + k0 + 4]);
            }
#pragma unroll
            for (int nt = 0; nt < 8; nt++) {
                const int n = warp_n * 64 + nt * 8 + g;
                bf[nt][0] = f2tf(smB[n * ASTRIDE + k0]);
                bf[nt][1] = f2tf(smB[n * ASTRIDE + k0 + 4]);
            }
#pragma unroll
            for (int mt = 0; mt < 4; mt++)
#pragma unroll
                for (int nt = 0; nt < 8; nt++)
                    mma_tf32(acc[mt][nt], af[mt], bf[nt]);
        }
        __syncthreads();
        const int nk = kc + 2;
        if (nk < NCHUNK) load_stage(kc & 1, nk * BK);
    }

    // ---- epilogue ----
    float* __restrict__ Dst = MEASURE ? g_meas : Outp;
#pragma unroll
    for (int mt = 0; mt < 4; mt++) {
#pragma unroll
        for (int nt = 0; nt < 8; nt++) {
            const int r0 = m_base + warp_m * 64 + mt * 16 + g;
            const int n0 = n_base + warp_n * 64 + nt * 8 + 2 * tig;
            const float* c = acc[mt][nt];
            if (MEASURE) {
                // each m16n8 tile spans exactly one 8-wide head (n0 base %8==0)
                const float2 lo = head_scan(c[0], c[1], tig);   // row r0
                const float2 hi = head_scan(c[2], c[3], tig);   // row r0+8
                *(float2*)(Dst + (size_t)r0 * KTOT + n0) = lo;
                *(float2*)(Dst + (size_t)(r0 + 8) * KTOT + n0) = hi;
            } else {
                *(float2*)(Dst + (size_t)r0 * KTOT + n0) =
                    make_float2(c[0], c[1]);
                *(float2*)(Dst + (size_t)(r0 + 8) * KTOT + n0) =
                    make_float2(c[2], c[3]);
            }
        }
    }
}

// ---------------------------------------------------------------------------
// Inputs (metadata order): x, Wq, Wk, Wv, Wo.  Wk/Wv are dead compute.
// ---------------------------------------------------------------------------
extern "C" void kernel_launch(void* const* d_in, const int* in_sizes, int n_in,
                              void* d_out, int out_size) {
    const float* x = (const float*)d_in[0];
    const float* Wq = (const float*)d_in[1];
    const float* Wo = (const float*)d_in[4];

    static bool attr_set = false;
    if (!attr_set) {
        cudaFuncSetAttribute(qgemm<true>,
                             cudaFuncAttributeMaxDynamicSharedMemorySize,
                             SMEM_BYTES);
        cudaFuncSetAttribute(qgemm<false>,
                             cudaFuncAttributeMaxDynamicSharedMemorySize,
                             SMEM_BYTES);
        attr_set = true;
    }

    dim3 grid(KTOT / BN, MTOT / BM);  // (4, 256): n fastest for L2 reuse of A
    qgemm<true><<<grid, 128, SMEM_BYTES>>>(x, Wq, nullptr);
    qgemm<false><<<grid, 128, SMEM_BYTES>>>(nullptr, Wo, (float*)d_out);
}